// round 14
// baseline (speedup 1.0000x reference)
#include <cuda_runtime.h>
#include <cstdint>
#include <cstddef>

// ============================================================================
// Llama4 MoE Router on sm_103 — two kernels:
//  K1 gemm:  logits = hs @ gate_w^T. tf32 mma.sync + cp.async 3-stage,
//            ks-level fragment double buffering. BM=64 -> 512 CTAs, 4 CTAs/SM
//            (single wave, ~28 warps/SM) to push DRAM past 57%.
//  K2 topk:  per-token (1 warp) top-3; near-ties refined IN-WARP with
//            double-float compensated fp32 dots (fp32 pipe only).
// Output (float32): [weights 32768*2][indices 32768*2][logits 32768*64]
// ============================================================================

#define TOKENS   32768
#define KDIM     4096
#define NEXP     64
#define BM       64
#define BK       32
#define NSTAGES  3
#define KITERS   (KDIM / BK)            // 128
#define THREADS  256
#define EPS      6e-3f

#define A_BYTES     (BM * BK * 4)       // 8192
#define B_BYTES     (NEXP * BK * 4)     // 8192
#define STAGE_BYTES (A_BYTES + B_BYTES) // 16384
#define SMEM_TOTAL  (NSTAGES * STAGE_BYTES)  // 49152 -> 4 CTAs/SM

__device__ __forceinline__ uint32_t smem_u32(const void* p) {
    uint32_t a;
    asm("{ .reg .u64 t; cvta.to.shared.u64 t, %1; cvt.u32.u64 %0, t; }" : "=r"(a) : "l"(p));
    return a;
}

__device__ __forceinline__ void cp16(uint32_t s, const void* g) {
    asm volatile("cp.async.cg.shared.global [%0], [%1], 16;" :: "r"(s), "l"(g) : "memory");
}

__device__ __forceinline__ void ldsm4(uint32_t& r0, uint32_t& r1, uint32_t& r2, uint32_t& r3,
                                      uint32_t addr) {
    asm volatile("ldmatrix.sync.aligned.m8n8.x4.shared.b16 {%0,%1,%2,%3}, [%4];"
                 : "=r"(r0), "=r"(r1), "=r"(r2), "=r"(r3) : "r"(addr));
}

__device__ __forceinline__ uint32_t rna_tf32(uint32_t x) {
    uint32_t r;
    asm("cvt.rna.tf32.f32 %0, %1;" : "=r"(r) : "f"(__uint_as_float(x)));
    return r;
}

__device__ __forceinline__ void mma8(float c[4], const uint32_t a[4], uint32_t b0, uint32_t b1) {
    asm volatile(
        "mma.sync.aligned.m16n8k8.row.col.f32.tf32.tf32.f32 "
        "{%0,%1,%2,%3}, {%4,%5,%6,%7}, {%8,%9}, {%0,%1,%2,%3};"
        : "+f"(c[0]), "+f"(c[1]), "+f"(c[2]), "+f"(c[3])
        : "r"(a[0]), "r"(a[1]), "r"(a[2]), "r"(a[3]), "r"(b0), "r"(b1));
}

// Error-free product + Knuth TwoSum accumulate: (s, c) += x*y (df-fp32).
__device__ __forceinline__ void dacc(float& s, float& c, float x, float y) {
    const float p = __fmul_rn(x, y);
    const float e = fmaf(x, y, -p);
    const float t = __fadd_rn(s, p);
    const float z = __fsub_rn(t, s);
    c = __fadd_rn(c, __fadd_rn(__fadd_rn(__fsub_rn(s, __fsub_rn(t, z)),
                                         __fsub_rn(p, z)), e));
    s = t;
}

// One K-chunk: A[64,32] + B[64,32] fp32 into stage s, 16B-chunk XOR swizzle.
__device__ __forceinline__ void load_stage(const float* __restrict__ hs,
                                           const float* __restrict__ gw,
                                           int m0, int kc, uint32_t sbase, int s, int tid) {
    const uint32_t ab = sbase + s * STAGE_BYTES;
    const uint32_t bb = ab + A_BYTES;
    #pragma unroll
    for (int j = 0; j < 2; j++) {                 // A: 512 chunks / 256 thr
        int c  = tid + j * 256;
        int r  = c >> 3;
        int ch = c & 7;
        cp16(ab + r * 128 + ((ch ^ (r & 7)) << 4),
             hs + (size_t)(m0 + r) * KDIM + kc + ch * 4);
    }
    #pragma unroll
    for (int j = 0; j < 2; j++) {                 // B: 512 chunks / 256 thr
        int c  = tid + j * 256;
        int e  = c >> 3;
        int ch = c & 7;
        cp16(bb + e * 128 + ((ch ^ (e & 7)) << 4),
             gw + (size_t)e * KDIM + kc + ch * 4);
    }
}

__global__ __launch_bounds__(THREADS, 4)
void gemm_kernel(const float* __restrict__ hs, const float* __restrict__ gw,
                 float* __restrict__ out) {
    extern __shared__ char smem[];
    const uint32_t sb = smem_u32(smem);
    const int tid  = threadIdx.x;
    const int wid  = tid >> 5;
    const int lane = tid & 31;
    const int m0   = blockIdx.x * BM;
    const int wm   = wid >> 2;            // 0..1 (M half: 32 rows)
    const int wn   = wid & 3;             // 0..3 (N quarter: 16 experts)
    const int lmat = lane >> 3;
    const int l8   = lane & 7;

    float c[2][2][4];
    #pragma unroll
    for (int mt = 0; mt < 2; mt++)
        #pragma unroll
        for (int nt = 0; nt < 2; nt++)
            #pragma unroll
            for (int q = 0; q < 4; q++) c[mt][nt][q] = 0.0f;

    #pragma unroll
    for (int j = 0; j < NSTAGES - 1; j++) {
        load_stage(hs, gw, m0, j * BK, sb, j, tid);
        asm volatile("cp.async.commit_group;" ::: "memory");
    }

    uint32_t af[2][2][4], bf[2][4];

    for (int i = 0; i < KITERS; i++) {
        asm volatile("cp.async.wait_group %0;" :: "n"(NSTAGES - 2) : "memory");
        __syncthreads();

        const uint32_t ab = sb + (i % NSTAGES) * STAGE_BYTES;
        const uint32_t bb = ab + A_BYTES;

        {   // fragments for ks=0 into buf 0
            #pragma unroll
            for (int mt = 0; mt < 2; mt++) {
                int r  = wm * 32 + mt * 16 + l8 + ((lmat & 1) << 3);
                int cc = (lmat >> 1);
                ldsm4(af[0][mt][0], af[0][mt][1], af[0][mt][2], af[0][mt][3],
                      ab + r * 128 + ((cc ^ (r & 7)) << 4));
            }
            {
                int r  = wn * 16 + l8 + ((lmat >> 1) << 3);
                int cc = (lmat & 1);
                ldsm4(bf[0][0], bf[0][1], bf[0][2], bf[0][3],
                      bb + r * 128 + ((cc ^ (r & 7)) << 4));
            }
            #pragma unroll
            for (int mt = 0; mt < 2; mt++)
                #pragma unroll
                for (int q = 0; q < 4; q++) af[0][mt][q] = rna_tf32(af[0][mt][q]);
            #pragma unroll
            for (int q = 0; q < 4; q++) bf[0][q] = rna_tf32(bf[0][q]);
        }

        #pragma unroll
        for (int ks = 0; ks < 4; ks++) {
            const int cur = ks & 1;
            const int nxt = cur ^ 1;

            if (ks < 3) {
                const int ck = (ks + 1) * 2;
                #pragma unroll
                for (int mt = 0; mt < 2; mt++) {
                    int r  = wm * 32 + mt * 16 + l8 + ((lmat & 1) << 3);
                    int cc = ck + (lmat >> 1);
                    ldsm4(af[nxt][mt][0], af[nxt][mt][1], af[nxt][mt][2], af[nxt][mt][3],
                          ab + r * 128 + ((cc ^ (r & 7)) << 4));
                }
                {
                    int r  = wn * 16 + l8 + ((lmat >> 1) << 3);
                    int cc = ck + (lmat & 1);
                    ldsm4(bf[nxt][0], bf[nxt][1], bf[nxt][2], bf[nxt][3],
                          bb + r * 128 + ((cc ^ (r & 7)) << 4));
                }
            }

            #pragma unroll
            for (int mt = 0; mt < 2; mt++)
                #pragma unroll
                for (int nt = 0; nt < 2; nt++)
                    mma8(c[mt][nt], af[cur][mt], bf[cur][nt * 2], bf[cur][nt * 2 + 1]);

            if (ks < 3) {
                #pragma unroll
                for (int mt = 0; mt < 2; mt++)
                    #pragma unroll
                    for (int q = 0; q < 4; q++) af[nxt][mt][q] = rna_tf32(af[nxt][mt][q]);
                #pragma unroll
                for (int q = 0; q < 4; q++) bf[nxt][q] = rna_tf32(bf[nxt][q]);
            }
        }

        const int kn = i + NSTAGES - 1;
        if (kn < KITERS) load_stage(hs, gw, m0, kn * BK, sb, kn % NSTAGES, tid);
        asm volatile("cp.async.commit_group;" ::: "memory");
    }

    // Logits straight from fragments.
    float* lg_out = out + 4 * TOKENS;
    const int g = lane >> 2, q = lane & 3;
    #pragma unroll
    for (int mt = 0; mt < 2; mt++) {
        const int r0 = wm * 32 + mt * 16 + g;
        #pragma unroll
        for (int nt = 0; nt < 2; nt++) {
            const int col = wn * 16 + nt * 8 + 2 * q;
            *reinterpret_cast<float2*>(lg_out + (size_t)(m0 + r0) * NEXP + col) =
                make_float2(c[mt][nt][0], c[mt][nt][1]);
            *reinterpret_cast<float2*>(lg_out + (size_t)(m0 + r0 + 8) * NEXP + col) =
                make_float2(c[mt][nt][2], c[mt][nt][3]);
        }
    }
}

// ============================================================================
// K2: one warp per token — top-3 select; near-ties refined in-warp with
// df-fp32 exact dots (candidate experts only).
// ============================================================================
__global__ __launch_bounds__(256, 4)
void topk_kernel(const float* __restrict__ hs, const float* __restrict__ gw,
                 float* __restrict__ out) {
    const int t    = (blockIdx.x * 256 + threadIdx.x) >> 5;
    const int lane = threadIdx.x & 31;
    const float* lg = out + 4 * TOKENS + (size_t)t * NEXP;

    const float2 v2 = *reinterpret_cast<const float2*>(lg + 2 * lane);
    float vals[2] = {v2.x, v2.y};
    int   idxs[2] = {2 * lane, 2 * lane + 1};
    bool  used[2] = {false, false};

    float m[3]; int mi[3];
    #pragma unroll
    for (int r = 0; r < 3; r++) {
        float bv = -1e30f; int bi = 9999;
        #pragma unroll
        for (int u = 0; u < 2; u++)
            if (!used[u] && (vals[u] > bv || (vals[u] == bv && idxs[u] < bi))) {
                bv = vals[u]; bi = idxs[u];
            }
        #pragma unroll
        for (int o = 16; o; o >>= 1) {
            float ov = __shfl_xor_sync(0xffffffffu, bv, o);
            int   oi = __shfl_xor_sync(0xffffffffu, bi, o);
            if (ov > bv || (ov == bv && oi < bi)) { bv = ov; bi = oi; }
        }
        m[r] = bv; mi[r] = bi;
        #pragma unroll
        for (int u = 0; u < 2; u++)
            if (idxs[u] == bi) used[u] = true;
    }

    if ((m[0] - m[1] >= EPS) && (m[1] - m[2] >= EPS)) {
        if (lane == 0) {
            const float e   = __expf(m[1] - m[0]);
            const float inv = 1.0f / (1.0f + e);
            *reinterpret_cast<float2*>(out + 2 * t) = make_float2(inv, e * inv);
            *reinterpret_cast<float2*>(out + 2 * TOKENS + 2 * t) =
                make_float2((float)mi[0], (float)mi[1]);
        }
        return;
    }

    // Near-tie: df-fp32 exact re-rank of candidates (logit >= m2 - EPS).
    const float thr = m[1] - EPS;
    const unsigned mask0 = __ballot_sync(0xffffffffu, vals[0] >= thr);
    const unsigned mask1 = __ballot_sync(0xffffffffu, vals[1] >= thr);

    double b1 = -1e300, b2 = -1e300;
    int j1 = 0, j2 = 0;
    const float4* ha = reinterpret_cast<const float4*>(hs + (size_t)t * KDIM);

    for (int l = 0; l < 32; l++) {
        #pragma unroll
        for (int u = 0; u < 2; u++) {
            const unsigned mm = u ? mask1 : mask0;
            if (!(mm & (1u << l))) continue;
            const int e = 2 * l + u;
            const float4* ga = reinterpret_cast<const float4*>(gw + (size_t)e * KDIM);
            float s0 = 0.f, c0 = 0.f, s1 = 0.f, c1 = 0.f;
            #pragma unroll 4
            for (int j = 0; j < 32; j++) {        // 32 x 32-lane strides = 1024 float4
                const int k = lane + j * 32;
                const float4 x = ha[k];
                const float4 y = ga[k];
                if (j & 1) {
                    dacc(s1, c1, x.x, y.x); dacc(s1, c1, x.y, y.y);
                    dacc(s1, c1, x.z, y.z); dacc(s1, c1, x.w, y.w);
                } else {
                    dacc(s0, c0, x.x, y.x); dacc(s0, c0, x.y, y.y);
                    dacc(s0, c0, x.z, y.z); dacc(s0, c0, x.w, y.w);
                }
            }
            double a = ((double)s0 + (double)s1) + ((double)c0 + (double)c1);
            #pragma unroll
            for (int o = 16; o; o >>= 1) a += __shfl_down_sync(0xffffffffu, a, o);
            a = __shfl_sync(0xffffffffu, a, 0);
            if (a > b1)      { b2 = b1; j2 = j1; b1 = a; j1 = e; }
            else if (a > b2) { b2 = a; j2 = e; }
        }
    }
    if (lane == 0) {
        const float e   = __expf((float)(b2 - b1));
        const float inv = 1.0f / (1.0f + e);
        *reinterpret_cast<float2*>(out + 2 * t) = make_float2(inv, e * inv);
        *reinterpret_cast<float2*>(out + 2 * TOKENS + 2 * t) =
            make_float2((float)j1, (float)j2);
    }
}

extern "C" void kernel_launch(void* const* d_in, const int* in_sizes, int n_in,
                              void* d_out, int out_size) {
    (void)in_sizes; (void)n_in; (void)out_size;
    const float* hs = (const float*)d_in[0];   // [32768, 4096]
    const float* gw = (const float*)d_in[1];   // [64, 4096]
    float* out = (float*)d_out;

    cudaFuncSetAttribute(gemm_kernel,
                         cudaFuncAttributeMaxDynamicSharedMemorySize, SMEM_TOTAL);
    gemm_kernel<<<TOKENS / BM, THREADS, SMEM_TOTAL>>>(hs, gw, out);
    topk_kernel<<<TOKENS * 32 / 256, 256>>>(hs, gw, out);
}

// round 15
// speedup vs baseline: 1.2558x; 1.2558x over previous
#include <cuda_runtime.h>
#include <cstdint>
#include <cstddef>

// ============================================================================
// Llama4 MoE Router on sm_103 — three kernels:
//  K1 gemm:   logits = hs @ gate_w^T (tf32 mma.sync, cp.async 4-stage,
//             ks-level fragment double buffering, BM=128). ~120 us.
//  K2 topk:   THREAD-per-token: 16 x float4 logit loads (MLP=16), register
//             top-3 scan; safe tokens finalized, near-ties enqueued.
//  K3 refine: 1 block per flagged token; candidate experts parallel across
//             warps; double-float compensated fp32 dots (fp32 pipe only).
// Output (float32): [weights 32768*2][indices 32768*2][logits 32768*64]
// ============================================================================

#define TOKENS   32768
#define KDIM     4096
#define NEXP     64
#define BM       128
#define BK       32
#define NSTAGES  4
#define KITERS   (KDIM / BK)            // 128
#define THREADS  256
#define EPS      6e-3f
#define RGRID    1024

#define A_BYTES     (BM * BK * 4)       // 16384
#define B_BYTES     (NEXP * BK * 4)     // 8192
#define STAGE_BYTES (A_BYTES + B_BYTES) // 24576
#define SMEM_TOTAL  (NSTAGES * STAGE_BYTES)  // 98304 (2 CTAs/SM resident)

// Refine worklist (device globals — no allocation).
__device__ int      d_count;
__device__ int      d_list[TOKENS];
__device__ unsigned d_mask0[TOKENS];
__device__ unsigned d_mask1[TOKENS];

__device__ __forceinline__ uint32_t smem_u32(const void* p) {
    uint32_t a;
    asm("{ .reg .u64 t; cvta.to.shared.u64 t, %1; cvt.u32.u64 %0, t; }" : "=r"(a) : "l"(p));
    return a;
}

__device__ __forceinline__ void cp16(uint32_t s, const void* g) {
    asm volatile("cp.async.cg.shared.global [%0], [%1], 16;" :: "r"(s), "l"(g) : "memory");
}

__device__ __forceinline__ void ldsm4(uint32_t& r0, uint32_t& r1, uint32_t& r2, uint32_t& r3,
                                      uint32_t addr) {
    asm volatile("ldmatrix.sync.aligned.m8n8.x4.shared.b16 {%0,%1,%2,%3}, [%4];"
                 : "=r"(r0), "=r"(r1), "=r"(r2), "=r"(r3) : "r"(addr));
}

__device__ __forceinline__ uint32_t rna_tf32(uint32_t x) {
    uint32_t r;
    asm("cvt.rna.tf32.f32 %0, %1;" : "=r"(r) : "f"(__uint_as_float(x)));
    return r;
}

__device__ __forceinline__ void mma8(float c[4], const uint32_t a[4], uint32_t b0, uint32_t b1) {
    asm volatile(
        "mma.sync.aligned.m16n8k8.row.col.f32.tf32.tf32.f32 "
        "{%0,%1,%2,%3}, {%4,%5,%6,%7}, {%8,%9}, {%0,%1,%2,%3};"
        : "+f"(c[0]), "+f"(c[1]), "+f"(c[2]), "+f"(c[3])
        : "r"(a[0]), "r"(a[1]), "r"(a[2]), "r"(a[3]), "r"(b0), "r"(b1));
}

// Error-free product + Knuth TwoSum accumulate: (s, c) += x*y (df-fp32).
__device__ __forceinline__ void dacc(float& s, float& c, float x, float y) {
    const float p = __fmul_rn(x, y);
    const float e = fmaf(x, y, -p);
    const float t = __fadd_rn(s, p);
    const float z = __fsub_rn(t, s);
    c = __fadd_rn(c, __fadd_rn(__fadd_rn(__fsub_rn(s, __fsub_rn(t, z)),
                                         __fsub_rn(p, z)), e));
    s = t;
}

__device__ __forceinline__ void load_stage(const float* __restrict__ hs,
                                           const float* __restrict__ gw,
                                           int m0, int kc, uint32_t sbase, int s, int tid) {
    const uint32_t ab = sbase + s * STAGE_BYTES;
    const uint32_t bb = ab + A_BYTES;
    #pragma unroll
    for (int j = 0; j < 4; j++) {
        int c  = tid + j * 256;
        int r  = c >> 3;
        int ch = c & 7;
        cp16(ab + r * 128 + ((ch ^ (r & 7)) << 4),
             hs + (size_t)(m0 + r) * KDIM + kc + ch * 4);
    }
    #pragma unroll
    for (int j = 0; j < 2; j++) {
        int c  = tid + j * 256;
        int e  = c >> 3;
        int ch = c & 7;
        cp16(bb + e * 128 + ((ch ^ (e & 7)) << 4),
             gw + (size_t)e * KDIM + kc + ch * 4);
    }
}

__global__ __launch_bounds__(THREADS, 2)
void gemm_kernel(const float* __restrict__ hs, const float* __restrict__ gw,
                 float* __restrict__ out) {
    if (blockIdx.x == 0 && threadIdx.x == 0) d_count = 0;   // reset worklist

    extern __shared__ char smem[];
    const uint32_t sb = smem_u32(smem);
    const int tid  = threadIdx.x;
    const int wid  = tid >> 5;
    const int lane = tid & 31;
    const int m0   = blockIdx.x * BM;
    const int wm   = wid >> 1;
    const int wn   = wid & 1;
    const int lmat = lane >> 3;
    const int l8   = lane & 7;

    float c[2][4][4];
    #pragma unroll
    for (int mt = 0; mt < 2; mt++)
        #pragma unroll
        for (int nt = 0; nt < 4; nt++)
            #pragma unroll
            for (int q = 0; q < 4; q++) c[mt][nt][q] = 0.0f;

    #pragma unroll
    for (int j = 0; j < NSTAGES - 1; j++) {
        load_stage(hs, gw, m0, j * BK, sb, j, tid);
        asm volatile("cp.async.commit_group;" ::: "memory");
    }

    uint32_t af[2][2][4], bf[2][2][4];

    for (int i = 0; i < KITERS; i++) {
        asm volatile("cp.async.wait_group %0;" :: "n"(NSTAGES - 2) : "memory");
        __syncthreads();

        const uint32_t ab = sb + (i % NSTAGES) * STAGE_BYTES;
        const uint32_t bb = ab + A_BYTES;

        {
            const int ck = 0;
            #pragma unroll
            for (int mt = 0; mt < 2; mt++) {
                int r  = wm * 32 + mt * 16 + l8 + ((lmat & 1) << 3);
                int cc = ck + (lmat >> 1);
                ldsm4(af[0][mt][0], af[0][mt][1], af[0][mt][2], af[0][mt][3],
                      ab + r * 128 + ((cc ^ (r & 7)) << 4));
            }
            #pragma unroll
            for (int p = 0; p < 2; p++) {
                int r  = wn * 32 + p * 16 + l8 + ((lmat >> 1) << 3);
                int cc = ck + (lmat & 1);
                ldsm4(bf[0][p][0], bf[0][p][1], bf[0][p][2], bf[0][p][3],
                      bb + r * 128 + ((cc ^ (r & 7)) << 4));
            }
            #pragma unroll
            for (int mt = 0; mt < 2; mt++)
                #pragma unroll
                for (int q = 0; q < 4; q++) af[0][mt][q] = rna_tf32(af[0][mt][q]);
            #pragma unroll
            for (int p = 0; p < 2; p++)
                #pragma unroll
                for (int q = 0; q < 4; q++) bf[0][p][q] = rna_tf32(bf[0][p][q]);
        }

        #pragma unroll
        for (int ks = 0; ks < 4; ks++) {
            const int cur = ks & 1;
            const int nxt = cur ^ 1;

            if (ks < 3) {
                const int ck = (ks + 1) * 2;
                #pragma unroll
                for (int mt = 0; mt < 2; mt++) {
                    int r  = wm * 32 + mt * 16 + l8 + ((lmat & 1) << 3);
                    int cc = ck + (lmat >> 1);
                    ldsm4(af[nxt][mt][0], af[nxt][mt][1], af[nxt][mt][2], af[nxt][mt][3],
                          ab + r * 128 + ((cc ^ (r & 7)) << 4));
                }
                #pragma unroll
                for (int p = 0; p < 2; p++) {
                    int r  = wn * 32 + p * 16 + l8 + ((lmat >> 1) << 3);
                    int cc = ck + (lmat & 1);
                    ldsm4(bf[nxt][p][0], bf[nxt][p][1], bf[nxt][p][2], bf[nxt][p][3],
                          bb + r * 128 + ((cc ^ (r & 7)) << 4));
                }
            }

            #pragma unroll
            for (int mt = 0; mt < 2; mt++)
                #pragma unroll
                for (int nt = 0; nt < 4; nt++)
                    mma8(c[mt][nt], af[cur][mt], bf[cur][nt >> 1][(nt & 1) * 2],
                                                 bf[cur][nt >> 1][(nt & 1) * 2 + 1]);

            if (ks < 3) {
                #pragma unroll
                for (int mt = 0; mt < 2; mt++)
                    #pragma unroll
                    for (int q = 0; q < 4; q++) af[nxt][mt][q] = rna_tf32(af[nxt][mt][q]);
                #pragma unroll
                for (int p = 0; p < 2; p++)
                    #pragma unroll
                    for (int q = 0; q < 4; q++) bf[nxt][p][q] = rna_tf32(bf[nxt][p][q]);
            }
        }

        const int kn = i + NSTAGES - 1;
        if (kn < KITERS) load_stage(hs, gw, m0, kn * BK, sb, kn % NSTAGES, tid);
        asm volatile("cp.async.commit_group;" ::: "memory");
    }

    float* lg_out = out + 4 * TOKENS;
    const int g = lane >> 2, q = lane & 3;
    #pragma unroll
    for (int mt = 0; mt < 2; mt++) {
        const int r0 = wm * 32 + mt * 16 + g;
        #pragma unroll
        for (int nt = 0; nt < 4; nt++) {
            const int col = wn * 32 + nt * 8 + 2 * q;
            *reinterpret_cast<float2*>(lg_out + (size_t)(m0 + r0) * NEXP + col) =
                make_float2(c[mt][nt][0], c[mt][nt][1]);
            *reinterpret_cast<float2*>(lg_out + (size_t)(m0 + r0 + 8) * NEXP + col) =
                make_float2(c[mt][nt][2], c[mt][nt][3]);
        }
    }
}

// ============================================================================
// K2: THREAD per token. 16 x float4 loads (MLP=16), register top-3 scan.
// Safe tokens finalized; near-ties re-read row (L1-hot) for masks + enqueue.
// ============================================================================
__global__ __launch_bounds__(256, 4)
void topk_kernel(float* __restrict__ out) {
    const int t = blockIdx.x * 256 + threadIdx.x;
    const float4* lg = reinterpret_cast<const float4*>(out + 4 * TOKENS + (size_t)t * NEXP);

    float m1 = -1e30f, m2 = -1e30f, m3 = -1e30f;
    int i1 = 0, i2 = 0;
    #pragma unroll
    for (int j = 0; j < 16; j++) {
        const float4 v = lg[j];
        const float vv[4] = {v.x, v.y, v.z, v.w};
        #pragma unroll
        for (int u = 0; u < 4; u++) {
            const int idx = 4 * j + u;
            if (vv[u] > m1)      { m3 = m2; m2 = m1; i2 = i1; m1 = vv[u]; i1 = idx; }
            else if (vv[u] > m2) { m3 = m2; m2 = vv[u]; i2 = idx; }
            else if (vv[u] > m3) { m3 = vv[u]; }
        }
    }

    if ((m1 - m2 >= EPS) && (m2 - m3 >= EPS)) {
        const float e   = __expf(m2 - m1);
        const float inv = 1.0f / (1.0f + e);
        *reinterpret_cast<float2*>(out + 2 * t) = make_float2(inv, e * inv);
        *reinterpret_cast<float2*>(out + 2 * TOKENS + 2 * t) =
            make_float2((float)i1, (float)i2);
        return;
    }

    // Near-tie (~4%): re-read row (L1/L2-hot) to build candidate masks.
    const float thr = m2 - EPS;
    unsigned mk0 = 0, mk1 = 0;
    #pragma unroll
    for (int j = 0; j < 16; j++) {
        const float4 v = lg[j];
        const float vv[4] = {v.x, v.y, v.z, v.w};
        #pragma unroll
        for (int u = 0; u < 4; u++) {
            const int e = 4 * j + u;
            if (vv[u] >= thr) {
                if (e & 1) mk1 |= 1u << (e >> 1);
                else       mk0 |= 1u << (e >> 1);
            }
        }
    }
    const int slot = atomicAdd(&d_count, 1);
    d_list[slot]  = t;
    d_mask0[slot] = mk0;
    d_mask1[slot] = mk1;
}

// ============================================================================
// K3: one block per flagged token; candidate experts distributed over the 8
// warps; per-lane df-fp32 accumulation; thread 0 picks top-2 from smem.
// ============================================================================
__global__ __launch_bounds__(256, 4)
void refine_kernel(const float* __restrict__ hs, const float* __restrict__ gw,
                   float* __restrict__ out) {
    __shared__ int    s_cand[NEXP];
    __shared__ int    s_ncand;
    __shared__ double s_val[NEXP];

    const int tid  = threadIdx.x;
    const int lane = tid & 31;
    const int wid  = tid >> 5;
    const int n    = d_count;

    for (int i = blockIdx.x; i < n; i += RGRID) {
        const int t = d_list[i];
        if (tid == 0) {
            const unsigned mk0 = d_mask0[i];
            const unsigned mk1 = d_mask1[i];
            int nc = 0;
            #pragma unroll
            for (int e = 0; e < NEXP; e++) {
                const unsigned mm = (e & 1) ? mk1 : mk0;
                if ((mm >> (e >> 1)) & 1u) s_cand[nc++] = e;
            }
            s_ncand = nc;
        }
        __syncthreads();

        const int nc = s_ncand;
        const float4* ha = reinterpret_cast<const float4*>(hs + (size_t)t * KDIM);

        for (int ci = wid; ci < nc; ci += 8) {
            const int e = s_cand[ci];
            const float4* ga = reinterpret_cast<const float4*>(gw + (size_t)e * KDIM);
            float s0 = 0.f, c0 = 0.f, s1 = 0.f, c1 = 0.f;
            #pragma unroll 4
            for (int j = 0; j < 32; j++) {        // 32 x 32-lane strides = 1024 float4
                const int k = lane + j * 32;
                const float4 x = ha[k];
                const float4 y = ga[k];
                if (j & 1) {
                    dacc(s1, c1, x.x, y.x); dacc(s1, c1, x.y, y.y);
                    dacc(s1, c1, x.z, y.z); dacc(s1, c1, x.w, y.w);
                } else {
                    dacc(s0, c0, x.x, y.x); dacc(s0, c0, x.y, y.y);
                    dacc(s0, c0, x.z, y.z); dacc(s0, c0, x.w, y.w);
                }
            }
            double a = ((double)s0 + (double)s1) + ((double)c0 + (double)c1);
            #pragma unroll
            for (int o = 16; o; o >>= 1) a += __shfl_down_sync(0xffffffffu, a, o);
            if (lane == 0) s_val[ci] = a;
        }
        __syncthreads();

        if (tid == 0) {
            double b1 = -1e300, b2 = -1e300;
            int j1 = 0, j2 = 0;
            for (int ci = 0; ci < nc; ci++) {
                const double v = s_val[ci];
                const int    e = s_cand[ci];
                if (v > b1)      { b2 = b1; j2 = j1; b1 = v; j1 = e; }
                else if (v > b2) { b2 = v; j2 = e; }
            }
            const float ex  = __expf((float)(b2 - b1));
            const float inv = 1.0f / (1.0f + ex);
            *reinterpret_cast<float2*>(out + 2 * t) = make_float2(inv, ex * inv);
            *reinterpret_cast<float2*>(out + 2 * TOKENS + 2 * t) =
                make_float2((float)j1, (float)j2);
        }
        __syncthreads();
    }
}

extern "C" void kernel_launch(void* const* d_in, const int* in_sizes, int n_in,
                              void* d_out, int out_size) {
    (void)in_sizes; (void)n_in; (void)out_size;
    const float* hs = (const float*)d_in[0];   // [32768, 4096]
    const float* gw = (const float*)d_in[1];   // [64, 4096]
    float* out = (float*)d_out;

    cudaFuncSetAttribute(gemm_kernel,
                         cudaFuncAttributeMaxDynamicSharedMemorySize, SMEM_TOTAL);
    gemm_kernel<<<TOKENS / BM, THREADS, SMEM_TOTAL>>>(hs, gw, out);
    topk_kernel<<<TOKENS / 256, 256>>>(out);
    refine_kernel<<<RGRID, 256>>>(hs, gw, out);
}

// round 16
// speedup vs baseline: 1.3986x; 1.1137x over previous
#include <cuda_runtime.h>
#include <cstdint>
#include <cstddef>

// ============================================================================
// Llama4 MoE Router on sm_103 — three kernels:
//  K1 gemm:   logits = hs @ gate_w^T (tf32 mma.sync, cp.async 4-stage,
//             ks-level fragment double buffering, BM=128). ~120 us.
//  K2 topk:   thread-per-token register top-3 scan; near-ties enqueued.
//  K3 refine: block per flagged token; hs row staged in smem ONCE, candidate
//             experts warp-parallel with fp32 4-acc dots (gw L2-resident).
// Output (float32): [weights 32768*2][indices 32768*2][logits 32768*64]
// ============================================================================

#define TOKENS   32768
#define KDIM     4096
#define NEXP     64
#define BM       128
#define BK       32
#define NSTAGES  4
#define KITERS   (KDIM / BK)            // 128
#define THREADS  256
#define EPS      6e-3f
#define RGRID    1024

#define A_BYTES     (BM * BK * 4)       // 16384
#define B_BYTES     (NEXP * BK * 4)     // 8192
#define STAGE_BYTES (A_BYTES + B_BYTES) // 24576
#define SMEM_TOTAL  (NSTAGES * STAGE_BYTES)  // 98304 (2 CTAs/SM resident)

// Refine worklist (device globals — no allocation).
__device__ int      d_count;
__device__ int      d_list[TOKENS];
__device__ unsigned d_mask0[TOKENS];
__device__ unsigned d_mask1[TOKENS];

__device__ __forceinline__ uint32_t smem_u32(const void* p) {
    uint32_t a;
    asm("{ .reg .u64 t; cvta.to.shared.u64 t, %1; cvt.u32.u64 %0, t; }" : "=r"(a) : "l"(p));
    return a;
}

__device__ __forceinline__ void cp16(uint32_t s, const void* g) {
    asm volatile("cp.async.cg.shared.global [%0], [%1], 16;" :: "r"(s), "l"(g) : "memory");
}

__device__ __forceinline__ void ldsm4(uint32_t& r0, uint32_t& r1, uint32_t& r2, uint32_t& r3,
                                      uint32_t addr) {
    asm volatile("ldmatrix.sync.aligned.m8n8.x4.shared.b16 {%0,%1,%2,%3}, [%4];"
                 : "=r"(r0), "=r"(r1), "=r"(r2), "=r"(r3) : "r"(addr));
}

__device__ __forceinline__ uint32_t rna_tf32(uint32_t x) {
    uint32_t r;
    asm("cvt.rna.tf32.f32 %0, %1;" : "=r"(r) : "f"(__uint_as_float(x)));
    return r;
}

__device__ __forceinline__ void mma8(float c[4], const uint32_t a[4], uint32_t b0, uint32_t b1) {
    asm volatile(
        "mma.sync.aligned.m16n8k8.row.col.f32.tf32.tf32.f32 "
        "{%0,%1,%2,%3}, {%4,%5,%6,%7}, {%8,%9}, {%0,%1,%2,%3};"
        : "+f"(c[0]), "+f"(c[1]), "+f"(c[2]), "+f"(c[3])
        : "r"(a[0]), "r"(a[1]), "r"(a[2]), "r"(a[3]), "r"(b0), "r"(b1));
}

__device__ __forceinline__ void load_stage(const float* __restrict__ hs,
                                           const float* __restrict__ gw,
                                           int m0, int kc, uint32_t sbase, int s, int tid) {
    const uint32_t ab = sbase + s * STAGE_BYTES;
    const uint32_t bb = ab + A_BYTES;
    #pragma unroll
    for (int j = 0; j < 4; j++) {
        int c  = tid + j * 256;
        int r  = c >> 3;
        int ch = c & 7;
        cp16(ab + r * 128 + ((ch ^ (r & 7)) << 4),
             hs + (size_t)(m0 + r) * KDIM + kc + ch * 4);
    }
    #pragma unroll
    for (int j = 0; j < 2; j++) {
        int c  = tid + j * 256;
        int e  = c >> 3;
        int ch = c & 7;
        cp16(bb + e * 128 + ((ch ^ (e & 7)) << 4),
             gw + (size_t)e * KDIM + kc + ch * 4);
    }
}

__global__ __launch_bounds__(THREADS, 2)
void gemm_kernel(const float* __restrict__ hs, const float* __restrict__ gw,
                 float* __restrict__ out) {
    if (blockIdx.x == 0 && threadIdx.x == 0) d_count = 0;   // reset worklist

    extern __shared__ char smem[];
    const uint32_t sb = smem_u32(smem);
    const int tid  = threadIdx.x;
    const int wid  = tid >> 5;
    const int lane = tid & 31;
    const int m0   = blockIdx.x * BM;
    const int wm   = wid >> 1;
    const int wn   = wid & 1;
    const int lmat = lane >> 3;
    const int l8   = lane & 7;

    float c[2][4][4];
    #pragma unroll
    for (int mt = 0; mt < 2; mt++)
        #pragma unroll
        for (int nt = 0; nt < 4; nt++)
            #pragma unroll
            for (int q = 0; q < 4; q++) c[mt][nt][q] = 0.0f;

    #pragma unroll
    for (int j = 0; j < NSTAGES - 1; j++) {
        load_stage(hs, gw, m0, j * BK, sb, j, tid);
        asm volatile("cp.async.commit_group;" ::: "memory");
    }

    uint32_t af[2][2][4], bf[2][2][4];

    for (int i = 0; i < KITERS; i++) {
        asm volatile("cp.async.wait_group %0;" :: "n"(NSTAGES - 2) : "memory");
        __syncthreads();

        const uint32_t ab = sb + (i % NSTAGES) * STAGE_BYTES;
        const uint32_t bb = ab + A_BYTES;

        {
            const int ck = 0;
            #pragma unroll
            for (int mt = 0; mt < 2; mt++) {
                int r  = wm * 32 + mt * 16 + l8 + ((lmat & 1) << 3);
                int cc = ck + (lmat >> 1);
                ldsm4(af[0][mt][0], af[0][mt][1], af[0][mt][2], af[0][mt][3],
                      ab + r * 128 + ((cc ^ (r & 7)) << 4));
            }
            #pragma unroll
            for (int p = 0; p < 2; p++) {
                int r  = wn * 32 + p * 16 + l8 + ((lmat >> 1) << 3);
                int cc = ck + (lmat & 1);
                ldsm4(bf[0][p][0], bf[0][p][1], bf[0][p][2], bf[0][p][3],
                      bb + r * 128 + ((cc ^ (r & 7)) << 4));
            }
            #pragma unroll
            for (int mt = 0; mt < 2; mt++)
                #pragma unroll
                for (int q = 0; q < 4; q++) af[0][mt][q] = rna_tf32(af[0][mt][q]);
            #pragma unroll
            for (int p = 0; p < 2; p++)
                #pragma unroll
                for (int q = 0; q < 4; q++) bf[0][p][q] = rna_tf32(bf[0][p][q]);
        }

        #pragma unroll
        for (int ks = 0; ks < 4; ks++) {
            const int cur = ks & 1;
            const int nxt = cur ^ 1;

            if (ks < 3) {
                const int ck = (ks + 1) * 2;
                #pragma unroll
                for (int mt = 0; mt < 2; mt++) {
                    int r  = wm * 32 + mt * 16 + l8 + ((lmat & 1) << 3);
                    int cc = ck + (lmat >> 1);
                    ldsm4(af[nxt][mt][0], af[nxt][mt][1], af[nxt][mt][2], af[nxt][mt][3],
                          ab + r * 128 + ((cc ^ (r & 7)) << 4));
                }
                #pragma unroll
                for (int p = 0; p < 2; p++) {
                    int r  = wn * 32 + p * 16 + l8 + ((lmat >> 1) << 3);
                    int cc = ck + (lmat & 1);
                    ldsm4(bf[nxt][p][0], bf[nxt][p][1], bf[nxt][p][2], bf[nxt][p][3],
                          bb + r * 128 + ((cc ^ (r & 7)) << 4));
                }
            }

            #pragma unroll
            for (int mt = 0; mt < 2; mt++)
                #pragma unroll
                for (int nt = 0; nt < 4; nt++)
                    mma8(c[mt][nt], af[cur][mt], bf[cur][nt >> 1][(nt & 1) * 2],
                                                 bf[cur][nt >> 1][(nt & 1) * 2 + 1]);

            if (ks < 3) {
                #pragma unroll
                for (int mt = 0; mt < 2; mt++)
                    #pragma unroll
                    for (int q = 0; q < 4; q++) af[nxt][mt][q] = rna_tf32(af[nxt][mt][q]);
                #pragma unroll
                for (int p = 0; p < 2; p++)
                    #pragma unroll
                    for (int q = 0; q < 4; q++) bf[nxt][p][q] = rna_tf32(bf[nxt][p][q]);
            }
        }

        const int kn = i + NSTAGES - 1;
        if (kn < KITERS) load_stage(hs, gw, m0, kn * BK, sb, kn % NSTAGES, tid);
        asm volatile("cp.async.commit_group;" ::: "memory");
    }

    float* lg_out = out + 4 * TOKENS;
    const int g = lane >> 2, q = lane & 3;
    #pragma unroll
    for (int mt = 0; mt < 2; mt++) {
        const int r0 = wm * 32 + mt * 16 + g;
        #pragma unroll
        for (int nt = 0; nt < 4; nt++) {
            const int col = wn * 32 + nt * 8 + 2 * q;
            *reinterpret_cast<float2*>(lg_out + (size_t)(m0 + r0) * NEXP + col) =
                make_float2(c[mt][nt][0], c[mt][nt][1]);
            *reinterpret_cast<float2*>(lg_out + (size_t)(m0 + r0 + 8) * NEXP + col) =
                make_float2(c[mt][nt][2], c[mt][nt][3]);
        }
    }
}

// ============================================================================
// K2: thread per token. 16 x float4 loads (MLP=16), register top-3 scan.
// Safe tokens finalized; near-ties re-read row (L1-hot) for masks + enqueue.
// ============================================================================
__global__ __launch_bounds__(256, 4)
void topk_kernel(float* __restrict__ out) {
    const int t = blockIdx.x * 256 + threadIdx.x;
    const float4* lg = reinterpret_cast<const float4*>(out + 4 * TOKENS + (size_t)t * NEXP);

    float m1 = -1e30f, m2 = -1e30f, m3 = -1e30f;
    int i1 = 0, i2 = 0;
    #pragma unroll
    for (int j = 0; j < 16; j++) {
        const float4 v = lg[j];
        const float vv[4] = {v.x, v.y, v.z, v.w};
        #pragma unroll
        for (int u = 0; u < 4; u++) {
            const int idx = 4 * j + u;
            if (vv[u] > m1)      { m3 = m2; m2 = m1; i2 = i1; m1 = vv[u]; i1 = idx; }
            else if (vv[u] > m2) { m3 = m2; m2 = vv[u]; i2 = idx; }
            else if (vv[u] > m3) { m3 = vv[u]; }
        }
    }

    if ((m1 - m2 >= EPS) && (m2 - m3 >= EPS)) {
        const float e   = __expf(m2 - m1);
        const float inv = 1.0f / (1.0f + e);
        *reinterpret_cast<float2*>(out + 2 * t) = make_float2(inv, e * inv);
        *reinterpret_cast<float2*>(out + 2 * TOKENS + 2 * t) =
            make_float2((float)i1, (float)i2);
        return;
    }

    const float thr = m2 - EPS;
    unsigned mk0 = 0, mk1 = 0;
    #pragma unroll
    for (int j = 0; j < 16; j++) {
        const float4 v = lg[j];
        const float vv[4] = {v.x, v.y, v.z, v.w};
        #pragma unroll
        for (int u = 0; u < 4; u++) {
            const int e = 4 * j + u;
            if (vv[u] >= thr) {
                if (e & 1) mk1 |= 1u << (e >> 1);
                else       mk0 |= 1u << (e >> 1);
            }
        }
    }
    const int slot = atomicAdd(&d_count, 1);
    d_list[slot]  = t;
    d_mask0[slot] = mk0;
    d_mask1[slot] = mk1;
}

// ============================================================================
// K3: block per flagged token. hs row staged into smem ONCE; candidate experts
// warp-parallel fp32 4-acc dots (hs from smem, gw from L2). Thread 0 top-2.
// ============================================================================
__global__ __launch_bounds__(256, 4)
void refine_kernel(const float* __restrict__ hs, const float* __restrict__ gw,
                   float* __restrict__ out) {
    __shared__ float s_hs[KDIM];        // 16 KB
    __shared__ int   s_cand[NEXP];
    __shared__ int   s_ncand;
    __shared__ float s_val[NEXP];

    const int tid  = threadIdx.x;
    const int lane = tid & 31;
    const int wid  = tid >> 5;
    const int n    = d_count;
    float4* sh4 = reinterpret_cast<float4*>(s_hs);

    for (int i = blockIdx.x; i < n; i += RGRID) {
        const int t = d_list[i];

        // Stage hs row (1024 float4 / 256 threads, coalesced).
        const float4* ha = reinterpret_cast<const float4*>(hs + (size_t)t * KDIM);
        #pragma unroll
        for (int j = 0; j < 4; j++)
            sh4[tid + j * 256] = ha[tid + j * 256];

        if (tid == 0) {
            const unsigned mk0 = d_mask0[i];
            const unsigned mk1 = d_mask1[i];
            int nc = 0;
            #pragma unroll
            for (int e = 0; e < NEXP; e++) {
                const unsigned mm = (e & 1) ? mk1 : mk0;
                if ((mm >> (e >> 1)) & 1u) s_cand[nc++] = e;
            }
            s_ncand = nc;
        }
        __syncthreads();

        const int nc = s_ncand;
        for (int ci = wid; ci < nc; ci += 8) {
            const int e = s_cand[ci];
            const float4* ga = reinterpret_cast<const float4*>(gw + (size_t)e * KDIM);
            float a0 = 0.f, a1 = 0.f, a2 = 0.f, a3 = 0.f;
            #pragma unroll 8
            for (int j = 0; j < 32; j++) {        // 32 x 32-lane strides = 1024 float4
                const int k = lane + j * 32;
                const float4 x = sh4[k];          // smem
                const float4 y = ga[k];           // L2-resident
                a0 = fmaf(x.x, y.x, a0); a1 = fmaf(x.y, y.y, a1);
                a2 = fmaf(x.z, y.z, a2); a3 = fmaf(x.w, y.w, a3);
            }
            float a = (a0 + a1) + (a2 + a3);
            #pragma unroll
            for (int o = 16; o; o >>= 1) a += __shfl_down_sync(0xffffffffu, a, o);
            if (lane == 0) s_val[ci] = a;
        }
        __syncthreads();

        if (tid == 0) {
            float b1 = -1e30f, b2 = -1e30f;
            int j1 = 0, j2 = 0;
            for (int ci = 0; ci < nc; ci++) {      // ascending expert id = tie-break
                const float v = s_val[ci];
                const int   e = s_cand[ci];
                if (v > b1)      { b2 = b1; j2 = j1; b1 = v; j1 = e; }
                else if (v > b2) { b2 = v; j2 = e; }
            }
            const float ex  = __expf(b2 - b1);
            const float inv = 1.0f / (1.0f + ex);
            *reinterpret_cast<float2*>(out + 2 * t) = make_float2(inv, ex * inv);
            *reinterpret_cast<float2*>(out + 2 * TOKENS + 2 * t) =
                make_float2((float)j1, (float)j2);
        }
        __syncthreads();
    }
}

extern "C" void kernel_launch(void* const* d_in, const int* in_sizes, int n_in,
                              void* d_out, int out_size) {
    (void)in_sizes; (void)n_in; (void)out_size;
    const float* hs = (const float*)d_in[0];   // [32768, 4096]
    const float* gw = (const float*)d_in[1];   // [64, 4096]
    float* out = (float*)d_out;

    cudaFuncSetAttribute(gemm_kernel,
                         cudaFuncAttributeMaxDynamicSharedMemorySize, SMEM_TOTAL);
    gemm_kernel<<<TOKENS / BM, THREADS, SMEM_TOTAL>>>(hs, gw, out);
    topk_kernel<<<TOKENS / 256, 256>>>(out);
    refine_kernel<<<RGRID, 256>>>(hs, gw, out);
}

// round 17
// speedup vs baseline: 1.4402x; 1.0298x over previous
#include <cuda_runtime.h>
#include <cstdint>
#include <cstddef>

// ============================================================================
// Llama4 MoE Router on sm_103 — four kernels:
//  K0 round:  pre-round gate_w to tf32 into a __device__ buffer (1 MB).
//  K1 gemm:   logits = hs @ gwt^T. tf32 mma.sync, cp.async 4-stage, ks-level
//             fragment double buffering. NO cvt in mainloop: B pre-rounded
//             (exact), A raw-truncated by HW.
//  K2 topk:   thread-per-token register top-3 scan; near-ties enqueued.
//  K3 refine: block per flagged token; hs row staged in smem; candidate
//             experts warp-parallel fp32 dots vs EXACT gw.
// Output (float32): [weights 32768*2][indices 32768*2][logits 32768*64]
// ============================================================================

#define TOKENS   32768
#define KDIM     4096
#define NEXP     64
#define BM       128
#define BK       32
#define NSTAGES  4
#define KITERS   (KDIM / BK)            // 128
#define THREADS  256
#define EPS      1e-2f
#define RGRID    1024

#define A_BYTES     (BM * BK * 4)       // 16384
#define B_BYTES     (NEXP * BK * 4)     // 8192
#define STAGE_BYTES (A_BYTES + B_BYTES) // 24576
#define SMEM_TOTAL  (NSTAGES * STAGE_BYTES)  // 98304 (2 CTAs/SM resident)

// Device globals — no allocation.
__device__ int      d_count;
__device__ int      d_list[TOKENS];
__device__ unsigned d_mask0[TOKENS];
__device__ unsigned d_mask1[TOKENS];
__device__ float    d_gwt[NEXP * KDIM];   // tf32-rounded gate_w (1 MB)

__device__ __forceinline__ uint32_t smem_u32(const void* p) {
    uint32_t a;
    asm("{ .reg .u64 t; cvta.to.shared.u64 t, %1; cvt.u32.u64 %0, t; }" : "=r"(a) : "l"(p));
    return a;
}

__device__ __forceinline__ void cp16(uint32_t s, const void* g) {
    asm volatile("cp.async.cg.shared.global [%0], [%1], 16;" :: "r"(s), "l"(g) : "memory");
}

__device__ __forceinline__ void ldsm4(uint32_t& r0, uint32_t& r1, uint32_t& r2, uint32_t& r3,
                                      uint32_t addr) {
    asm volatile("ldmatrix.sync.aligned.m8n8.x4.shared.b16 {%0,%1,%2,%3}, [%4];"
                 : "=r"(r0), "=r"(r1), "=r"(r2), "=r"(r3) : "r"(addr));
}

__device__ __forceinline__ float rna_tf32f(float x) {
    uint32_t r;
    asm("cvt.rna.tf32.f32 %0, %1;" : "=r"(r) : "f"(x));
    return __uint_as_float(r);
}

__device__ __forceinline__ void mma8(float c[4], const uint32_t a[4], uint32_t b0, uint32_t b1) {
    asm volatile(
        "mma.sync.aligned.m16n8k8.row.col.f32.tf32.tf32.f32 "
        "{%0,%1,%2,%3}, {%4,%5,%6,%7}, {%8,%9}, {%0,%1,%2,%3};"
        : "+f"(c[0]), "+f"(c[1]), "+f"(c[2]), "+f"(c[3])
        : "r"(a[0]), "r"(a[1]), "r"(a[2]), "r"(a[3]), "r"(b0), "r"(b1));
}

// K0: round gate_w to tf32 (rna) once per launch. 262144 elems.
__global__ __launch_bounds__(256)
void round_gw_kernel(const float* __restrict__ gw) {
    const int i = blockIdx.x * 256 + threadIdx.x;   // 65536 threads
    if (i == 0) d_count = 0;                        // reset worklist here too
    #pragma unroll
    for (int j = 0; j < 4; j++) {
        const int idx = i + j * 65536;
        d_gwt[idx] = rna_tf32f(gw[idx]);
    }
}

__device__ __forceinline__ void load_stage(const float* __restrict__ hs,
                                           int m0, int kc, uint32_t sbase, int s, int tid) {
    const uint32_t ab = sbase + s * STAGE_BYTES;
    const uint32_t bb = ab + A_BYTES;
    #pragma unroll
    for (int j = 0; j < 4; j++) {
        int c  = tid + j * 256;
        int r  = c >> 3;
        int ch = c & 7;
        cp16(ab + r * 128 + ((ch ^ (r & 7)) << 4),
             hs + (size_t)(m0 + r) * KDIM + kc + ch * 4);
    }
    #pragma unroll
    for (int j = 0; j < 2; j++) {
        int c  = tid + j * 256;
        int e  = c >> 3;
        int ch = c & 7;
        cp16(bb + e * 128 + ((ch ^ (e & 7)) << 4),
             &d_gwt[(size_t)e * KDIM + kc + ch * 4]);
    }
}

__global__ __launch_bounds__(THREADS, 2)
void gemm_kernel(const float* __restrict__ hs, float* __restrict__ out) {
    extern __shared__ char smem[];
    const uint32_t sb = smem_u32(smem);
    const int tid  = threadIdx.x;
    const int wid  = tid >> 5;
    const int lane = tid & 31;
    const int m0   = blockIdx.x * BM;
    const int wm   = wid >> 1;
    const int wn   = wid & 1;
    const int lmat = lane >> 3;
    const int l8   = lane & 7;

    float c[2][4][4];
    #pragma unroll
    for (int mt = 0; mt < 2; mt++)
        #pragma unroll
        for (int nt = 0; nt < 4; nt++)
            #pragma unroll
            for (int q = 0; q < 4; q++) c[mt][nt][q] = 0.0f;

    #pragma unroll
    for (int j = 0; j < NSTAGES - 1; j++) {
        load_stage(hs, m0, j * BK, sb, j, tid);
        asm volatile("cp.async.commit_group;" ::: "memory");
    }

    uint32_t af[2][2][4], bf[2][2][4];

    for (int i = 0; i < KITERS; i++) {
        asm volatile("cp.async.wait_group %0;" :: "n"(NSTAGES - 2) : "memory");
        __syncthreads();

        const uint32_t ab = sb + (i % NSTAGES) * STAGE_BYTES;
        const uint32_t bb = ab + A_BYTES;

        {   // fragments for ks=0 into buf 0 (no cvt — A raw, B pre-rounded)
            #pragma unroll
            for (int mt = 0; mt < 2; mt++) {
                int r  = wm * 32 + mt * 16 + l8 + ((lmat & 1) << 3);
                int cc = (lmat >> 1);
                ldsm4(af[0][mt][0], af[0][mt][1], af[0][mt][2], af[0][mt][3],
                      ab + r * 128 + ((cc ^ (r & 7)) << 4));
            }
            #pragma unroll
            for (int p = 0; p < 2; p++) {
                int r  = wn * 32 + p * 16 + l8 + ((lmat >> 1) << 3);
                int cc = (lmat & 1);
                ldsm4(bf[0][p][0], bf[0][p][1], bf[0][p][2], bf[0][p][3],
                      bb + r * 128 + ((cc ^ (r & 7)) << 4));
            }
        }

        #pragma unroll
        for (int ks = 0; ks < 4; ks++) {
            const int cur = ks & 1;
            const int nxt = cur ^ 1;

            if (ks < 3) {
                const int ck = (ks + 1) * 2;
                #pragma unroll
                for (int mt = 0; mt < 2; mt++) {
                    int r  = wm * 32 + mt * 16 + l8 + ((lmat & 1) << 3);
                    int cc = ck + (lmat >> 1);
                    ldsm4(af[nxt][mt][0], af[nxt][mt][1], af[nxt][mt][2], af[nxt][mt][3],
                          ab + r * 128 + ((cc ^ (r & 7)) << 4));
                }
                #pragma unroll
                for (int p = 0; p < 2; p++) {
                    int r  = wn * 32 + p * 16 + l8 + ((lmat >> 1) << 3);
                    int cc = ck + (lmat & 1);
                    ldsm4(bf[nxt][p][0], bf[nxt][p][1], bf[nxt][p][2], bf[nxt][p][3],
                          bb + r * 128 + ((cc ^ (r & 7)) << 4));
                }
            }

            #pragma unroll
            for (int mt = 0; mt < 2; mt++)
                #pragma unroll
                for (int nt = 0; nt < 4; nt++)
                    mma8(c[mt][nt], af[cur][mt], bf[cur][nt >> 1][(nt & 1) * 2],
                                                 bf[cur][nt >> 1][(nt & 1) * 2 + 1]);
        }

        const int kn = i + NSTAGES - 1;
        if (kn < KITERS) load_stage(hs, m0, kn * BK, sb, kn % NSTAGES, tid);
        asm volatile("cp.async.commit_group;" ::: "memory");
    }

    float* lg_out = out + 4 * TOKENS;
    const int g = lane >> 2, q = lane & 3;
    #pragma unroll
    for (int mt = 0; mt < 2; mt++) {
        const int r0 = wm * 32 + mt * 16 + g;
        #pragma unroll
        for (int nt = 0; nt < 4; nt++) {
            const int col = wn * 32 + nt * 8 + 2 * q;
            *reinterpret_cast<float2*>(lg_out + (size_t)(m0 + r0) * NEXP + col) =
                make_float2(c[mt][nt][0], c[mt][nt][1]);
            *reinterpret_cast<float2*>(lg_out + (size_t)(m0 + r0 + 8) * NEXP + col) =
                make_float2(c[mt][nt][2], c[mt][nt][3]);
        }
    }
}

// ============================================================================
// K2: thread per token. 16 x float4 loads (MLP=16), register top-3 scan.
// ============================================================================
__global__ __launch_bounds__(256, 4)
void topk_kernel(float* __restrict__ out) {
    const int t = blockIdx.x * 256 + threadIdx.x;
    const float4* lg = reinterpret_cast<const float4*>(out + 4 * TOKENS + (size_t)t * NEXP);

    float m1 = -1e30f, m2 = -1e30f, m3 = -1e30f;
    int i1 = 0, i2 = 0;
    #pragma unroll
    for (int j = 0; j < 16; j++) {
        const float4 v = lg[j];
        const float vv[4] = {v.x, v.y, v.z, v.w};
        #pragma unroll
        for (int u = 0; u < 4; u++) {
            const int idx = 4 * j + u;
            if (vv[u] > m1)      { m3 = m2; m2 = m1; i2 = i1; m1 = vv[u]; i1 = idx; }
            else if (vv[u] > m2) { m3 = m2; m2 = vv[u]; i2 = idx; }
            else if (vv[u] > m3) { m3 = vv[u]; }
        }
    }

    if ((m1 - m2 >= EPS) && (m2 - m3 >= EPS)) {
        const float e   = __expf(m2 - m1);
        const float inv = 1.0f / (1.0f + e);
        *reinterpret_cast<float2*>(out + 2 * t) = make_float2(inv, e * inv);
        *reinterpret_cast<float2*>(out + 2 * TOKENS + 2 * t) =
            make_float2((float)i1, (float)i2);
        return;
    }

    const float thr = m2 - EPS;
    unsigned mk0 = 0, mk1 = 0;
    #pragma unroll
    for (int j = 0; j < 16; j++) {
        const float4 v = lg[j];
        const float vv[4] = {v.x, v.y, v.z, v.w};
        #pragma unroll
        for (int u = 0; u < 4; u++) {
            const int e = 4 * j + u;
            if (vv[u] >= thr) {
                if (e & 1) mk1 |= 1u << (e >> 1);
                else       mk0 |= 1u << (e >> 1);
            }
        }
    }
    const int slot = atomicAdd(&d_count, 1);
    d_list[slot]  = t;
    d_mask0[slot] = mk0;
    d_mask1[slot] = mk1;
}

// ============================================================================
// K3: block per flagged token; hs row staged in smem; candidate experts
// warp-parallel fp32 4-acc dots vs EXACT gw (L2-resident).
// ============================================================================
__global__ __launch_bounds__(256, 4)
void refine_kernel(const float* __restrict__ hs, const float* __restrict__ gw,
                   float* __restrict__ out) {
    __shared__ float s_hs[KDIM];        // 16 KB
    __shared__ int   s_cand[NEXP];
    __shared__ int   s_ncand;
    __shared__ float s_val[NEXP];

    const int tid  = threadIdx.x;
    const int lane = tid & 31;
    const int wid  = tid >> 5;
    const int n    = d_count;
    float4* sh4 = reinterpret_cast<float4*>(s_hs);

    for (int i = blockIdx.x; i < n; i += RGRID) {
        const int t = d_list[i];

        const float4* ha = reinterpret_cast<const float4*>(hs + (size_t)t * KDIM);
        #pragma unroll
        for (int j = 0; j < 4; j++)
            sh4[tid + j * 256] = ha[tid + j * 256];

        if (tid == 0) {
            const unsigned mk0 = d_mask0[i];
            const unsigned mk1 = d_mask1[i];
            int nc = 0;
            #pragma unroll
            for (int e = 0; e < NEXP; e++) {
                const unsigned mm = (e & 1) ? mk1 : mk0;
                if ((mm >> (e >> 1)) & 1u) s_cand[nc++] = e;
            }
            s_ncand = nc;
        }
        __syncthreads();

        const int nc = s_ncand;
        for (int ci = wid; ci < nc; ci += 8) {
            const int e = s_cand[ci];
            const float4* ga = reinterpret_cast<const float4*>(gw + (size_t)e * KDIM);
            float a0 = 0.f, a1 = 0.f, a2 = 0.f, a3 = 0.f;
            #pragma unroll 8
            for (int j = 0; j < 32; j++) {
                const int k = lane + j * 32;
                const float4 x = sh4[k];
                const float4 y = ga[k];
                a0 = fmaf(x.x, y.x, a0); a1 = fmaf(x.y, y.y, a1);
                a2 = fmaf(x.z, y.z, a2); a3 = fmaf(x.w, y.w, a3);
            }
            float a = (a0 + a1) + (a2 + a3);
            #pragma unroll
            for (int o = 16; o; o >>= 1) a += __shfl_down_sync(0xffffffffu, a, o);
            if (lane == 0) s_val[ci] = a;
        }
        __syncthreads();

        if (tid == 0) {
            float b1 = -1e30f, b2 = -1e30f;
            int j1 = 0, j2 = 0;
            for (int ci = 0; ci < nc; ci++) {
                const float v = s_val[ci];
                const int   e = s_cand[ci];
                if (v > b1)      { b2 = b1; j2 = j1; b1 = v; j1 = e; }
                else if (v > b2) { b2 = v; j2 = e; }
            }
            const float ex  = __expf(b2 - b1);
            const float inv = 1.0f / (1.0f + ex);
            *reinterpret_cast<float2*>(out + 2 * t) = make_float2(inv, ex * inv);
            *reinterpret_cast<float2*>(out + 2 * TOKENS + 2 * t) =
                make_float2((float)j1, (float)j2);
        }
        __syncthreads();
    }
}

extern "C" void kernel_launch(void* const* d_in, const int* in_sizes, int n_in,
                              void* d_out, int out_size) {
    (void)in_sizes; (void)n_in; (void)out_size;
    const float* hs = (const float*)d_in[0];   // [32768, 4096]
    const float* gw = (const float*)d_in[1];   // [64, 4096]
    float* out = (float*)d_out;

    cudaFuncSetAttribute(gemm_kernel,
                         cudaFuncAttributeMaxDynamicSharedMemorySize, SMEM_TOTAL);
    round_gw_kernel<<<256, 256>>>(gw);
    gemm_kernel<<<TOKENS / BM, THREADS, SMEM_TOTAL>>>(hs, out);
    topk_kernel<<<TOKENS / 256, 256>>>(out);
    refine_kernel<<<RGRID, 256>>>(hs, gw, out);
}